// round 1
// baseline (speedup 1.0000x reference)
#include <cuda_runtime.h>
#include <math.h>

#define S_LEN   8192
#define BATCH   4
#define DMODEL  1024
#define NROWS   (BATCH * S_LEN)   // 32768
#define NHEADS  16
#define DHEAD   64

// Scratch (device globals: allocation-free per harness rules)
__device__ float g_q[(size_t)NROWS * DMODEL];
__device__ float g_k[(size_t)NROWS * DMODEL];
__device__ float g_v[(size_t)NROWS * DMODEL];
__device__ float g_attn[(size_t)NROWS * DMODEL];
__device__ float g_kv[BATCH * NHEADS * DHEAD * DHEAD];   // [b,h,dv,dk]
__device__ float g_ksum[BATCH * NHEADS * DHEAD];

// ---------------------------------------------------------------------------
// tf32 helpers
// ---------------------------------------------------------------------------
__device__ __forceinline__ unsigned f2tf(float f) {
    unsigned u;
    asm("cvt.rna.tf32.f32 %0, %1;" : "=r"(u) : "f"(f));
    return u;
}

__device__ __forceinline__ void mma_tf32(float* c, const unsigned* a, const unsigned* b) {
    asm volatile(
        "mma.sync.aligned.m16n8k8.row.col.f32.tf32.tf32.f32 "
        "{%0,%1,%2,%3}, {%4,%5,%6,%7}, {%8,%9}, {%0,%1,%2,%3};"
        : "+f"(c[0]), "+f"(c[1]), "+f"(c[2]), "+f"(c[3])
        : "r"(a[0]), "r"(a[1]), "r"(a[2]), "r"(a[3]), "r"(b[0]), "r"(b[1]));
}

// ---------------------------------------------------------------------------
// Zero kernel (for atomic accumulators)
// ---------------------------------------------------------------------------
__global__ void zero_kernel(float* p, int n) {
    int i = blockIdx.x * blockDim.x + threadIdx.x;
    if (i < n) p[i] = 0.0f;
}

// ---------------------------------------------------------------------------
// GEMM: C[M,1024] = A[M,1024] @ W[1024,1024]^T + bias, optional elu+1 epilogue
// A row-major (K contiguous), W row-major [out,in] (K contiguous) -> row.col mma
// BM=128, BN=128, BK=32, 256 threads, 8 warps (2x4), warp tile 64x32
// ---------------------------------------------------------------------------
#define BM 128
#define BN 128
#define BK 32
#define LDS_PAD 36   // BK + 4 pad

template <int EPI>
__global__ void __launch_bounds__(256)
gemm_tf32_kernel(const float* __restrict__ A, const float* __restrict__ W,
                 const float* __restrict__ bias, float* __restrict__ C) {
    __shared__ float As[BM * LDS_PAD];
    __shared__ float Bs[BN * LDS_PAD];

    const int tid  = threadIdx.x;
    const int lane = tid & 31;
    const int warp = tid >> 5;
    const int wm   = (warp & 1) * 64;   // warp row offset in tile
    const int wn   = (warp >> 1) * 32;  // warp col offset in tile
    const int m0   = blockIdx.y * BM;
    const int n0   = blockIdx.x * BN;
    const int g    = lane >> 2;         // groupID 0..7
    const int tg   = lane & 3;          // thread-in-group 0..3

    float acc[4][4][4];
#pragma unroll
    for (int mt = 0; mt < 4; mt++)
#pragma unroll
        for (int nt = 0; nt < 4; nt++)
#pragma unroll
            for (int i = 0; i < 4; i++) acc[mt][nt][i] = 0.0f;

    for (int k0 = 0; k0 < DMODEL; k0 += BK) {
        __syncthreads();
        // load A and B tiles (each 128x32 fp32, 1024 float4 per tile)
#pragma unroll
        for (int i = 0; i < 4; i++) {
            int idx = tid + i * 256;
            int r   = idx >> 3;
            int c4  = (idx & 7) << 2;
            float4 va = *(const float4*)&A[(size_t)(m0 + r) * DMODEL + k0 + c4];
            *(float4*)&As[r * LDS_PAD + c4] = va;
            float4 vb = *(const float4*)&W[(size_t)(n0 + r) * DMODEL + k0 + c4];
            *(float4*)&Bs[r * LDS_PAD + c4] = vb;
        }
        __syncthreads();

#pragma unroll
        for (int ks = 0; ks < 4; ks++) {
            const int kk = ks * 8;
            unsigned a[4][4], b[4][2];
#pragma unroll
            for (int mt = 0; mt < 4; mt++) {
                int rb = wm + mt * 16;
                a[mt][0] = f2tf(As[(rb + g)     * LDS_PAD + kk + tg]);
                a[mt][1] = f2tf(As[(rb + g + 8) * LDS_PAD + kk + tg]);
                a[mt][2] = f2tf(As[(rb + g)     * LDS_PAD + kk + tg + 4]);
                a[mt][3] = f2tf(As[(rb + g + 8) * LDS_PAD + kk + tg + 4]);
            }
#pragma unroll
            for (int nt = 0; nt < 4; nt++) {
                int cb = wn + nt * 8;
                b[nt][0] = f2tf(Bs[(cb + g) * LDS_PAD + kk + tg]);
                b[nt][1] = f2tf(Bs[(cb + g) * LDS_PAD + kk + tg + 4]);
            }
#pragma unroll
            for (int mt = 0; mt < 4; mt++)
#pragma unroll
                for (int nt = 0; nt < 4; nt++)
                    mma_tf32(acc[mt][nt], a[mt], b[nt]);
        }
    }

    // epilogue: bias + optional elu(x)+1 feature map, float2 stores
#pragma unroll
    for (int mt = 0; mt < 4; mt++) {
#pragma unroll
        for (int nt = 0; nt < 4; nt++) {
            int row = m0 + wm + mt * 16 + g;
            int col = n0 + wn + nt * 8 + 2 * tg;
            float bv0 = bias[col];
            float bv1 = bias[col + 1];
            float v00 = acc[mt][nt][0] + bv0;
            float v01 = acc[mt][nt][1] + bv1;
            float v10 = acc[mt][nt][2] + bv0;
            float v11 = acc[mt][nt][3] + bv1;
            if (EPI) {
                v00 = (v00 > 0.0f) ? v00 + 1.0f : expf(v00);
                v01 = (v01 > 0.0f) ? v01 + 1.0f : expf(v01);
                v10 = (v10 > 0.0f) ? v10 + 1.0f : expf(v10);
                v11 = (v11 > 0.0f) ? v11 + 1.0f : expf(v11);
            }
            float2 o0 = make_float2(v00, v01);
            float2 o1 = make_float2(v10, v11);
            *(float2*)&C[(size_t)row * DMODEL + col]       = o0;
            *(float2*)&C[(size_t)(row + 8) * DMODEL + col] = o1;
        }
    }
}

// ---------------------------------------------------------------------------
// KV chain: kv[b,h,i,j] = sum_s V[b,s,h,i] * K[b,s,h,j];  ksum[b,h,j] = sum_s K
// grid (64 bh, 8 s-chunks of 1024), 256 threads (16x16), each thread 4x4 outer product
// ---------------------------------------------------------------------------
__global__ void __launch_bounds__(256)
kv_kernel(const float* __restrict__ K, const float* __restrict__ V,
          float* __restrict__ kv, float* __restrict__ ksum) {
    const int bh = blockIdx.x;              // b*NHEADS + h
    const int b  = bh / NHEADS;
    const int h  = bh % NHEADS;
    const int tid = threadIdx.x;
    const int ty  = tid >> 4;
    const int tx  = tid & 15;

    __shared__ float Ks[16][64];
    __shared__ float Vs[16][64];

    float acc[4][4];
#pragma unroll
    for (int i = 0; i < 4; i++)
#pragma unroll
        for (int j = 0; j < 4; j++) acc[i][j] = 0.0f;
    float ks_acc = 0.0f;

    const float* Kbase = K + (size_t)b * S_LEN * DMODEL + h * DHEAD;
    const float* Vbase = V + (size_t)b * S_LEN * DMODEL + h * DHEAD;
    const int s0 = blockIdx.y * (S_LEN / 8);

    for (int s = s0; s < s0 + (S_LEN / 8); s += 16) {
        __syncthreads();
        {
            int r  = tid >> 4;
            int c4 = (tid & 15) << 2;
            *(float4*)&Ks[r][c4] = *(const float4*)&Kbase[(size_t)(s + r) * DMODEL + c4];
            *(float4*)&Vs[r][c4] = *(const float4*)&Vbase[(size_t)(s + r) * DMODEL + c4];
        }
        __syncthreads();
        if (tid < 64) {
#pragma unroll
            for (int ss = 0; ss < 16; ss++) ks_acc += Ks[ss][tid];
        }
#pragma unroll
        for (int ss = 0; ss < 16; ss++) {
            float vr[4], kr[4];
#pragma unroll
            for (int i = 0; i < 4; i++) vr[i] = Vs[ss][ty * 4 + i];
#pragma unroll
            for (int j = 0; j < 4; j++) kr[j] = Ks[ss][tx * 4 + j];
#pragma unroll
            for (int i = 0; i < 4; i++)
#pragma unroll
                for (int j = 0; j < 4; j++) acc[i][j] += vr[i] * kr[j];
        }
    }

    float* kvbh = kv + (size_t)bh * DHEAD * DHEAD;
#pragma unroll
    for (int i = 0; i < 4; i++)
#pragma unroll
        for (int j = 0; j < 4; j++)
            atomicAdd(&kvbh[(ty * 4 + i) * DHEAD + tx * 4 + j], acc[i][j]);
    if (tid < 64) atomicAdd(&ksum[bh * DHEAD + tid], ks_acc);
}

// ---------------------------------------------------------------------------
// Attention apply: attn[t, h*64+i] = norm * sum_d q[t,h,d] * kv[b,h,i,d]
// norm = 1/(sum_d q[t,h,d]*ksum[b,h,d] + eps)
// grid (NROWS/128, NHEADS), 128 threads, one row per thread
// ---------------------------------------------------------------------------
__global__ void __launch_bounds__(128)
attn_kernel(const float* __restrict__ Q, const float* __restrict__ kv,
            const float* __restrict__ ksum, float* __restrict__ attn) {
    const int h   = blockIdx.y;
    const int row = blockIdx.x * 128 + threadIdx.x;
    const int b   = row / S_LEN;

    __shared__ float kvs[64][64];
    __shared__ float kss[64];

    const float* kvsrc = kv + (size_t)(b * NHEADS + h) * DHEAD * DHEAD;
    for (int i = threadIdx.x; i < (DHEAD * DHEAD) / 4; i += 128)
        ((float4*)kvs)[i] = ((const float4*)kvsrc)[i];
    if (threadIdx.x < 64) kss[threadIdx.x] = ksum[(b * NHEADS + h) * DHEAD + threadIdx.x];
    __syncthreads();

    float q[64];
    const float* qp = Q + (size_t)row * DMODEL + h * DHEAD;
#pragma unroll
    for (int i = 0; i < 16; i++) ((float4*)q)[i] = ((const float4*)qp)[i];

    float nd = 0.0f;
#pragma unroll
    for (int d = 0; d < 64; d++) nd += q[d] * kss[d];
    const float norm = 1.0f / (nd + 1e-6f);

    float* op = attn + (size_t)row * DMODEL + h * DHEAD;
    for (int i0 = 0; i0 < 64; i0 += 4) {
        float out[4];
#pragma unroll
        for (int u = 0; u < 4; u++) {
            float s = 0.0f;
#pragma unroll
            for (int d = 0; d < 64; d++) s += q[d] * kvs[i0 + u][d];
            out[u] = s * norm;
        }
        *(float4*)&op[i0] = make_float4(out[0], out[1], out[2], out[3]);
    }
}

// ---------------------------------------------------------------------------
// Launch
// ---------------------------------------------------------------------------
extern "C" void kernel_launch(void* const* d_in, const int* in_sizes, int n_in,
                              void* d_out, int out_size) {
    const float* query = (const float*)d_in[0];
    const float* key_  = (const float*)d_in[1];
    const float* value = (const float*)d_in[2];
    const float* Wq = (const float*)d_in[3];
    const float* bq = (const float*)d_in[4];
    const float* Wk = (const float*)d_in[5];
    const float* bk = (const float*)d_in[6];
    const float* Wv = (const float*)d_in[7];
    const float* bv = (const float*)d_in[8];
    const float* Wo = (const float*)d_in[9];
    const float* bo = (const float*)d_in[10];
    float* out = (float*)d_out;

    float *qf, *kf, *vf, *attn, *kv, *ks;
    cudaGetSymbolAddress((void**)&qf,   g_q);
    cudaGetSymbolAddress((void**)&kf,   g_k);
    cudaGetSymbolAddress((void**)&vf,   g_v);
    cudaGetSymbolAddress((void**)&attn, g_attn);
    cudaGetSymbolAddress((void**)&kv,   g_kv);
    cudaGetSymbolAddress((void**)&ks,   g_ksum);

    // zero accumulators for atomics
    zero_kernel<<<(BATCH * NHEADS * DHEAD * DHEAD + 255) / 256, 256>>>(kv, BATCH * NHEADS * DHEAD * DHEAD);
    zero_kernel<<<(BATCH * NHEADS * DHEAD + 255) / 256, 256>>>(ks, BATCH * NHEADS * DHEAD);

    dim3 gemm_grid(DMODEL / BN, NROWS / BM);  // (8, 256)
    gemm_tf32_kernel<1><<<gemm_grid, 256>>>(query, Wq, bq, qf);
    gemm_tf32_kernel<1><<<gemm_grid, 256>>>(key_,  Wk, bk, kf);
    gemm_tf32_kernel<0><<<gemm_grid, 256>>>(value, Wv, bv, vf);

    kv_kernel<<<dim3(BATCH * NHEADS, 8), 256>>>(kf, vf, kv, ks);

    attn_kernel<<<dim3(NROWS / 128, NHEADS), 128>>>(qf, kv, ks, attn);

    gemm_tf32_kernel<0><<<gemm_grid, 256>>>(attn, Wo, bo, out);
}